// round 1
// baseline (speedup 1.0000x reference)
#include <cuda_runtime.h>
#include <cuda_bf16.h>
#include <math.h>

#define MAX_T 11
#define HIDDEN 768
#define MAX_S 64
#define MAX_ROWS 64

// Scratch (no allocations allowed): per-row weight, per-slice offset/count.
__device__ float g_w[MAX_ROWS];
__device__ int   g_off[MAX_S + 1];
__device__ int   g_ns[MAX_S];

// ---------------------------------------------------------------------------
// K1: tiny control kernel. One block.
//  - cumsum slice_mask -> offsets
//  - logits[s,t] = dot(hist[idx], W) + b  for valid t, exp-masked
//  - probs = softmax over valid turns, written to out_probs
//  - per-row weight w[r] = probs[seg(r), pad(seg)+pos(r)] -> g_w
// ---------------------------------------------------------------------------
__global__ void k_probs(const float* __restrict__ hist,
                        const float* __restrict__ W,
                        const float* __restrict__ b,
                        const int*   __restrict__ slice_mask,
                        float* __restrict__ out_probs,
                        int rows, int S)
{
    __shared__ float s_exp[MAX_S * MAX_T];   // exp-masked logits
    __shared__ float s_probs[MAX_S * MAX_T];
    __shared__ int   s_off[MAX_S + 1];
    __shared__ int   s_ns[MAX_S];

    int tid = threadIdx.x;

    if (tid == 0) {
        int acc = 0;
        for (int s = 0; s < S; s++) {
            s_off[s] = acc;
            int n = slice_mask[s];
            s_ns[s] = n;
            g_off[s] = acc;
            g_ns[s] = n;
            acc += n;
        }
        s_off[S] = acc;
        g_off[S] = acc;
    }
    __syncthreads();

    // 176 dot products of length 768: one (s,t) per warp iteration.
    int warp = tid >> 5, lane = tid & 31;
    int nwarps = blockDim.x >> 5;
    float b0 = b[0];
    for (int i = warp; i < S * MAX_T; i += nwarps) {
        int s = i / MAX_T, t = i - s * MAX_T;
        int pad = MAX_T - s_ns[s];
        float e = 0.f;
        if (t >= pad) {
            int idx = s_off[s] + t - pad;       // guaranteed in [0, rows)
            if (idx < 0) idx = 0;
            if (idx >= rows) idx = rows - 1;
            const float* h = hist + (size_t)idx * HIDDEN;
            float v = 0.f;
            #pragma unroll 4
            for (int c = lane; c < HIDDEN; c += 32) v += h[c] * W[c];
            #pragma unroll
            for (int o = 16; o; o >>= 1) v += __shfl_xor_sync(0xffffffffu, v, o);
            e = __expf(v + b0);
        }
        if (lane == 0) s_exp[i] = e;
    }
    __syncthreads();

    // per-slice normalize (one thread per slice) and emit probs
    if (tid < S) {
        float sum = 0.f;
        #pragma unroll
        for (int t = 0; t < MAX_T; t++) sum += s_exp[tid * MAX_T + t];
        float inv = 1.f / sum;
        #pragma unroll
        for (int t = 0; t < MAX_T; t++) {
            float p = s_exp[tid * MAX_T + t] * inv;
            s_probs[tid * MAX_T + t] = p;
            out_probs[tid * MAX_T + t] = p;
        }
    }
    __syncthreads();

    // per-row weight
    if (tid < rows) {
        int seg = S - 1;
        for (int s = 0; s < S; s++) {
            if (tid < s_off[s + 1]) { seg = s; break; }
        }
        int pos = tid - s_off[seg];
        int tt = (MAX_T - s_ns[seg]) + pos;
        if (tt < 0) tt = 0;
        if (tt > MAX_T - 1) tt = MAX_T - 1;
        g_w[tid] = s_probs[seg * MAX_T + tt];
    }
}

// ---------------------------------------------------------------------------
// K2: weighted segment sum, float4-vectorized. Used for both bert and mtl.
// out[s][j] = sum_{k<ns[s]} w[off[s]+k] * in[off[s]+k][j]
// vec_per_row = (elements per row) / 4
// ---------------------------------------------------------------------------
__global__ void k_segsum(const float4* __restrict__ in,
                         float4* __restrict__ out,
                         int vec_per_row)
{
    int s = blockIdx.y;
    int j = blockIdx.x * blockDim.x + threadIdx.x;
    if (j >= vec_per_row) return;

    int off = g_off[s];
    int n   = g_ns[s];

    float4 acc = make_float4(0.f, 0.f, 0.f, 0.f);
    #pragma unroll 4
    for (int k = 0; k < n; k++) {
        float w = g_w[off + k];
        float4 v = in[(size_t)(off + k) * vec_per_row + j];
        acc.x += w * v.x;
        acc.y += w * v.y;
        acc.z += w * v.z;
        acc.w += w * v.w;
    }
    out[(size_t)s * vec_per_row + j] = acc;
}

extern "C" void kernel_launch(void* const* d_in, const int* in_sizes, int n_in,
                              void* d_out, int out_size)
{
    const float* bert       = (const float*)d_in[0];
    const float* hist       = (const float*)d_in[1];
    const float* mtl        = (const float*)d_in[2];
    const float* W          = (const float*)d_in[3];
    const float* b          = (const float*)d_in[4];
    const int*   slice_mask = (const int*)  d_in[5];

    int rows = in_sizes[1] / HIDDEN;                 // 64
    int seqh = in_sizes[0] / rows;                   // 512*768 per bert row
    int per_s = seqh + HIDDEN + MAX_T;               // output elems per slice
    int S = out_size / per_s;                        // 16

    float* out        = (float*)d_out;
    float* out_bert   = out;
    float* out_mtl    = out_bert + (size_t)S * seqh;
    float* out_probs  = out_mtl  + (size_t)S * HIDDEN;

    k_probs<<<1, 128>>>(hist, W, b, slice_mask, out_probs, rows, S);

    int vec_bert = seqh / 4;                         // 98304
    dim3 gb((vec_bert + 255) / 256, S);
    k_segsum<<<gb, 256>>>((const float4*)bert, (float4*)out_bert, vec_bert);

    int vec_mtl = HIDDEN / 4;                        // 192
    k_segsum<<<dim3(1, S), vec_mtl>>>((const float4*)mtl, (float4*)out_mtl, vec_mtl);
}

// round 2
// speedup vs baseline: 2.7544x; 2.7544x over previous
#include <cuda_runtime.h>
#include <cuda_bf16.h>
#include <math.h>

#define MAX_T 11
#define HIDDEN 768
#define MAX_S 64
#define MAX_ROWS 64

// Scratch (no device allocation allowed)
__device__ float g_exp[MAX_S * MAX_T];   // exp-masked logits
__device__ float g_w[MAX_ROWS];          // per-row weight
__device__ int   g_off[MAX_S + 1];
__device__ int   g_ns[MAX_S];

// ---------------------------------------------------------------------------
// K1: one block per (s,t) pair. 192 threads, one float4 each -> full MLP,
// one DRAM round trip instead of a serial chain.
// ---------------------------------------------------------------------------
__global__ void k_dots(const float* __restrict__ hist,
                       const float* __restrict__ W,
                       const float* __restrict__ b,
                       const int*   __restrict__ slice_mask,
                       int rows, int S)
{
    __shared__ int   s_mask[MAX_S];
    __shared__ int   s_offs[MAX_S];
    __shared__ float s_red[6];

    int tid = threadIdx.x;
    int i = blockIdx.x;                 // 0 .. S*MAX_T-1
    int s = i / MAX_T, t = i - s * MAX_T;

    if (tid < S) s_mask[tid] = slice_mask[tid];
    __syncthreads();
    if (tid == 0) {
        int acc = 0;
        for (int k = 0; k < S; k++) { s_offs[k] = acc; acc += s_mask[k]; }
    }
    __syncthreads();

    int ns  = s_mask[s];
    int pad = MAX_T - ns;
    if (t < pad) {
        if (tid == 0) g_exp[i] = 0.f;
        return;
    }
    int idx = s_offs[s] + t - pad;
    if (idx < 0) idx = 0;
    if (idx >= rows) idx = rows - 1;

    const float4* h4 = (const float4*)(hist + (size_t)idx * HIDDEN);
    const float4* w4 = (const float4*)W;
    float4 hv = h4[tid];
    float4 wv = w4[tid];
    float v = hv.x * wv.x + hv.y * wv.y + hv.z * wv.z + hv.w * wv.w;

    // reduce across 192 threads (6 warps)
    #pragma unroll
    for (int o = 16; o; o >>= 1) v += __shfl_xor_sync(0xffffffffu, v, o);
    int warp = tid >> 5, lane = tid & 31;
    if (lane == 0) s_red[warp] = v;
    __syncthreads();
    if (tid == 0) {
        float tot = s_red[0] + s_red[1] + s_red[2] + s_red[3] + s_red[4] + s_red[5];
        g_exp[i] = __expf(tot + b[0]);
    }
}

// ---------------------------------------------------------------------------
// K2: finalize. One block: offsets, softmax, out_probs, per-row weights.
// Reads g_exp (L2-hot), slice_mask (L2-hot). ~2us.
// ---------------------------------------------------------------------------
__global__ void k_final(const int* __restrict__ slice_mask,
                        float* __restrict__ out_probs,
                        int rows, int S)
{
    __shared__ float s_probs[MAX_S * MAX_T];
    __shared__ int   s_off[MAX_S + 1];
    __shared__ int   s_ns[MAX_S];
    __shared__ int   s_mask[MAX_S];

    int tid = threadIdx.x;
    if (tid < S) s_mask[tid] = slice_mask[tid];
    __syncthreads();
    if (tid == 0) {
        int acc = 0;
        for (int k = 0; k < S; k++) {
            s_off[k] = acc; g_off[k] = acc;
            s_ns[k] = s_mask[k]; g_ns[k] = s_mask[k];
            acc += s_mask[k];
        }
        s_off[S] = acc; g_off[S] = acc;
    }
    __syncthreads();

    if (tid < S) {
        float e[MAX_T];
        float sum = 0.f;
        #pragma unroll
        for (int t = 0; t < MAX_T; t++) { e[t] = g_exp[tid * MAX_T + t]; sum += e[t]; }
        float inv = 1.f / sum;
        #pragma unroll
        for (int t = 0; t < MAX_T; t++) {
            float p = e[t] * inv;
            s_probs[tid * MAX_T + t] = p;
            out_probs[tid * MAX_T + t] = p;
        }
    }
    __syncthreads();

    if (tid < rows) {
        int seg = S - 1;
        for (int s = 0; s < S; s++) {
            if (tid < s_off[s + 1]) { seg = s; break; }
        }
        int pos = tid - s_off[seg];
        int tt = (MAX_T - s_ns[seg]) + pos;
        if (tt < 0) tt = 0;
        if (tt > MAX_T - 1) tt = MAX_T - 1;
        g_w[tid] = s_probs[seg * MAX_T + tt];
    }
}

// ---------------------------------------------------------------------------
// K3: weighted segment sum, float4-vectorized. blockIdx.x < bert_blocks does
// bert; the last x-slot does mtl (folded to save a launch).
// ---------------------------------------------------------------------------
__global__ void k_segsum(const float4* __restrict__ bert,
                         float4* __restrict__ out_bert,
                         const float4* __restrict__ mtl,
                         float4* __restrict__ out_mtl,
                         int vec_bert, int vec_mtl, int bert_blocks)
{
    int s = blockIdx.y;
    int off = g_off[s];
    int n   = g_ns[s];

    const float4* in;
    float4* out;
    int vec, j;
    if (blockIdx.x < (unsigned)bert_blocks) {
        in = bert; out = out_bert; vec = vec_bert;
        j = blockIdx.x * blockDim.x + threadIdx.x;
    } else {
        in = mtl; out = out_mtl; vec = vec_mtl;
        j = threadIdx.x;
    }
    if (j >= vec) return;

    float4 acc = make_float4(0.f, 0.f, 0.f, 0.f);
    #pragma unroll 4
    for (int k = 0; k < n; k++) {
        float w = g_w[off + k];
        float4 v = in[(size_t)(off + k) * vec + j];
        acc.x += w * v.x;
        acc.y += w * v.y;
        acc.z += w * v.z;
        acc.w += w * v.w;
    }
    out[(size_t)s * vec + j] = acc;
}

extern "C" void kernel_launch(void* const* d_in, const int* in_sizes, int n_in,
                              void* d_out, int out_size)
{
    const float* bert       = (const float*)d_in[0];
    const float* hist       = (const float*)d_in[1];
    const float* mtl        = (const float*)d_in[2];
    const float* W          = (const float*)d_in[3];
    const float* b          = (const float*)d_in[4];
    const int*   slice_mask = (const int*)  d_in[5];

    int rows = in_sizes[1] / HIDDEN;                 // 64
    int seqh = in_sizes[0] / rows;                   // 512*768
    int per_s = seqh + HIDDEN + MAX_T;
    int S = out_size / per_s;                        // 16

    float* out        = (float*)d_out;
    float* out_bert   = out;
    float* out_mtl    = out_bert + (size_t)S * seqh;
    float* out_probs  = out_mtl  + (size_t)S * HIDDEN;

    k_dots<<<S * MAX_T, HIDDEN / 4>>>(hist, W, b, slice_mask, rows, S);
    k_final<<<1, 128>>>(slice_mask, out_probs, rows, S);

    int vec_bert = seqh / 4;                         // 98304
    int vec_mtl  = HIDDEN / 4;                       // 192
    int bert_blocks = (vec_bert + 255) / 256;        // 384
    dim3 g(bert_blocks + 1, S);
    k_segsum<<<g, 256>>>((const float4*)bert, (float4*)out_bert,
                         (const float4*)mtl, (float4*)out_mtl,
                         vec_bert, vec_mtl, bert_blocks);
}